// round 1
// baseline (speedup 1.0000x reference)
#include <cuda_runtime.h>
#include <math.h>

#define TOKENS   8192
#define DIM      4096
#define NEXP     256
#define TOPK     8
#define NGROUPS  8
#define TOPKG    4
#define ROUTE_SCALE 2.5f

// scratch: sigmoid scores [TOKENS][NEXP]
__device__ float g_scores[TOKENS * NEXP];

// ---------------- GEMM (fp32) + sigmoid ----------------
#define BM 128
#define BN 128
#define BK 16

__global__ __launch_bounds__(256, 1)
void gemm_sigmoid_kernel(const float* __restrict__ x, const float* __restrict__ W) {
    __shared__ float As[BK][BM];
    __shared__ float Bs[BK][BN];

    const int tid = threadIdx.x;
    const int bm = blockIdx.y * BM;
    const int bn = blockIdx.x * BN;
    const int tx = tid & 15;   // n-dim thread coord
    const int ty = tid >> 4;   // m-dim thread coord

    const int lrow = tid >> 2;  // 0..63
    const int lk4  = tid & 3;   // which float4 along K (covers BK=16)

    const float4* __restrict__ xv = reinterpret_cast<const float4*>(x);
    const float4* __restrict__ wv = reinterpret_cast<const float4*>(W);
    const int ld4 = DIM / 4;

    float acc[8][8];
    #pragma unroll
    for (int i = 0; i < 8; i++)
        #pragma unroll
        for (int j = 0; j < 8; j++) acc[i][j] = 0.0f;

    // prefetch first K-tile into registers
    float4 pa0 = xv[(size_t)(bm + lrow) * ld4 + lk4];
    float4 pa1 = xv[(size_t)(bm + 64 + lrow) * ld4 + lk4];
    float4 pb0 = wv[(size_t)(bn + lrow) * ld4 + lk4];
    float4 pb1 = wv[(size_t)(bn + 64 + lrow) * ld4 + lk4];

    for (int k0 = 0; k0 < DIM; k0 += BK) {
        // commit prefetched tile to smem
        As[lk4 * 4 + 0][lrow] = pa0.x;
        As[lk4 * 4 + 1][lrow] = pa0.y;
        As[lk4 * 4 + 2][lrow] = pa0.z;
        As[lk4 * 4 + 3][lrow] = pa0.w;
        As[lk4 * 4 + 0][64 + lrow] = pa1.x;
        As[lk4 * 4 + 1][64 + lrow] = pa1.y;
        As[lk4 * 4 + 2][64 + lrow] = pa1.z;
        As[lk4 * 4 + 3][64 + lrow] = pa1.w;
        Bs[lk4 * 4 + 0][lrow] = pb0.x;
        Bs[lk4 * 4 + 1][lrow] = pb0.y;
        Bs[lk4 * 4 + 2][lrow] = pb0.z;
        Bs[lk4 * 4 + 3][lrow] = pb0.w;
        Bs[lk4 * 4 + 0][64 + lrow] = pb1.x;
        Bs[lk4 * 4 + 1][64 + lrow] = pb1.y;
        Bs[lk4 * 4 + 2][64 + lrow] = pb1.z;
        Bs[lk4 * 4 + 3][64 + lrow] = pb1.w;
        __syncthreads();

        // prefetch next K-tile (overlaps with compute below)
        if (k0 + BK < DIM) {
            const int kb = (k0 + BK) >> 2;
            pa0 = xv[(size_t)(bm + lrow) * ld4 + kb + lk4];
            pa1 = xv[(size_t)(bm + 64 + lrow) * ld4 + kb + lk4];
            pb0 = wv[(size_t)(bn + lrow) * ld4 + kb + lk4];
            pb1 = wv[(size_t)(bn + 64 + lrow) * ld4 + kb + lk4];
        }

        #pragma unroll
        for (int k = 0; k < BK; k++) {
            float4 a0 = *reinterpret_cast<const float4*>(&As[k][ty * 8]);
            float4 a1 = *reinterpret_cast<const float4*>(&As[k][ty * 8 + 4]);
            float4 b0 = *reinterpret_cast<const float4*>(&Bs[k][tx * 8]);
            float4 b1 = *reinterpret_cast<const float4*>(&Bs[k][tx * 8 + 4]);
            float ra[8] = {a0.x, a0.y, a0.z, a0.w, a1.x, a1.y, a1.z, a1.w};
            float rb[8] = {b0.x, b0.y, b0.z, b0.w, b1.x, b1.y, b1.z, b1.w};
            #pragma unroll
            for (int i = 0; i < 8; i++)
                #pragma unroll
                for (int j = 0; j < 8; j++)
                    acc[i][j] = fmaf(ra[i], rb[j], acc[i][j]);
        }
        __syncthreads();
    }

    // epilogue: sigmoid -> scores buffer
    #pragma unroll
    for (int i = 0; i < 8; i++) {
        const int t = bm + ty * 8 + i;
        #pragma unroll
        for (int j = 0; j < 8; j++) {
            const int e = bn + tx * 8 + j;
            const float v = acc[i][j];
            g_scores[(size_t)t * NEXP + e] = 1.0f / (1.0f + __expf(-v));
        }
    }
}

// ---------------- Routing: one warp per token ----------------
__global__ __launch_bounds__(256)
void route_kernel(const float* __restrict__ bias, float* __restrict__ out, int out_size) {
    const int warp = threadIdx.x >> 5;
    const int lane = threadIdx.x & 31;
    const int t = blockIdx.x * 8 + warp;
    if (t >= TOKENS) return;

    const float* srow = g_scores + (size_t)t * NEXP;

    // lane l owns experts [8l, 8l+8); group = lane >> 2 (32 experts per group)
    float sv[8], sb[8];
    {
        float4 v0 = *reinterpret_cast<const float4*>(srow + lane * 8);
        float4 v1 = *reinterpret_cast<const float4*>(srow + lane * 8 + 4);
        float4 c0 = *reinterpret_cast<const float4*>(bias + lane * 8);
        float4 c1 = *reinterpret_cast<const float4*>(bias + lane * 8 + 4);
        sv[0] = v0.x; sv[1] = v0.y; sv[2] = v0.z; sv[3] = v0.w;
        sv[4] = v1.x; sv[5] = v1.y; sv[6] = v1.z; sv[7] = v1.w;
        sb[0] = sv[0] + c0.x; sb[1] = sv[1] + c0.y; sb[2] = sv[2] + c0.z; sb[3] = sv[3] + c0.w;
        sb[4] = sv[4] + c1.x; sb[5] = sv[5] + c1.y; sb[6] = sv[6] + c1.z; sb[7] = sv[7] + c1.w;
    }

    // per-lane top-2 of biased scores
    float a = -INFINITY, b2 = -INFINITY;
    #pragma unroll
    for (int j = 0; j < 8; j++) {
        float v = sb[j];
        if (v > a)       { b2 = a; a = v; }
        else if (v > b2) { b2 = v; }
    }
    // merge top-2 across the 4 lanes of the group
    #pragma unroll
    for (int off = 1; off <= 2; off <<= 1) {
        float oa = __shfl_xor_sync(0xffffffffu, a, off);
        float ob = __shfl_xor_sync(0xffffffffu, b2, off);
        float m  = fmaxf(a, oa);
        float s2 = fmaxf(fminf(a, oa), fmaxf(b2, ob));
        a = m; b2 = s2;
    }
    const float gscore = a + b2;

    // all lanes gather the 8 group scores
    float g[8];
    #pragma unroll
    for (int gg = 0; gg < 8; gg++)
        g[gg] = __shfl_sync(0xffffffffu, gscore, gg * 4);

    // top-4 groups (tie -> lower group index, matching jax top_k stability)
    unsigned gmask = 0;
    #pragma unroll
    for (int r = 0; r < TOPKG; r++) {
        float bv = -INFINITY; int bi = 0;
        #pragma unroll
        for (int gg = 0; gg < 8; gg++) {
            bool sel = !((gmask >> gg) & 1u) && (g[gg] > bv);
            if (sel) { bv = g[gg]; bi = gg; }
        }
        gmask |= 1u << bi;
    }

    // mask: multiply-by-zero semantics (masked entries become exactly 0.0)
    const bool keep = (gmask >> (lane >> 2)) & 1u;
    #pragma unroll
    for (int j = 0; j < 8; j++) sb[j] = keep ? sb[j] : 0.0f;

    // top-8 over 256 masked scores (tie -> lower expert index)
    int my_idx = 0; float my_w = 0.0f;
    #pragma unroll
    for (int r = 0; r < TOPK; r++) {
        float lv = sb[0]; int lj = 0;
        #pragma unroll
        for (int j = 1; j < 8; j++)
            if (sb[j] > lv) { lv = sb[j]; lj = j; }
        float v = lv; int e = lane * 8 + lj;
        #pragma unroll
        for (int off = 16; off; off >>= 1) {
            float ov = __shfl_xor_sync(0xffffffffu, v, off);
            int   oe = __shfl_xor_sync(0xffffffffu, e, off);
            if (ov > v || (ov == v && oe < e)) { v = ov; e = oe; }
        }
        // owner lane clears the winner and provides the ORIGINAL sigmoid score
        float w = 0.0f;
        if ((e >> 3) == lane) {
            const int j = e & 7;
            #pragma unroll
            for (int jj = 0; jj < 8; jj++)
                if (jj == j) { w = sv[jj]; sb[jj] = -INFINITY; }
        }
        w = __shfl_sync(0xffffffffu, w, e >> 3);
        if (lane == r) { my_idx = e; my_w = w; }
    }

    // renormalize selected weights, scale by 2.5
    float ws = (lane < TOPK) ? my_w : 0.0f;
    #pragma unroll
    for (int off = 16; off; off >>= 1)
        ws += __shfl_xor_sync(0xffffffffu, ws, off);

    if (lane < TOPK) {
        const float wfin = my_w / ws * ROUTE_SCALE;
        out[(size_t)t * TOPK + lane] = wfin;
        if (out_size >= 2 * TOKENS * TOPK)
            out[(size_t)TOKENS * TOPK + (size_t)t * TOPK + lane] = (float)my_idx;
    }
}

extern "C" void kernel_launch(void* const* d_in, const int* in_sizes, int n_in,
                              void* d_out, int out_size) {
    const float* x    = (const float*)d_in[0];
    const float* W    = (const float*)d_in[1];
    const float* bias = (const float*)d_in[2];

    dim3 grid(NEXP / BN, TOKENS / BM);  // (2, 64)
    gemm_sigmoid_kernel<<<grid, 256>>>(x, W);
    route_kernel<<<TOKENS / 8, 256>>>(bias, (float*)d_out, out_size);
}

// round 6
// speedup vs baseline: 2.4462x; 2.4462x over previous
#include <cuda_runtime.h>
#include <cuda_fp16.h>
#include <math.h>
#include <stdint.h>

#define TOKENS   8192
#define DIM      4096
#define NEXP     256
#define TOPK     8
#define TOPKG    4
#define ROUTE_SCALE 2.5f
#define WSCALE   64.0f
#define RSCALE   2048.0f            // residual pre-scale (2^11) -> no fp16 subnormals
#define INV_RS   (1.0f/2048.0f)
#define INV_WSCALE (1.0f/64.0f)

#define BM 64
#define BN 256
#define KB 64                       // K elements per stage
#define NCHUNK (DIM/KB)             // 64

#define A_STAGE_B (BM*KB*2)         // 8192 B
#define B_STAGE_B (BN*KB*2)         // 32768 B
#define STAGE_B   (A_STAGE_B + B_STAGE_B)   // 40960 B
#define SMEM_TOTAL (3*STAGE_B)      // 122880 B
#define SROW 260                    // score smem row stride (floats)

// ---------------- device scratch (fp16 split operands) ----------------
__device__ __half g_xh[(size_t)TOKENS*DIM];
__device__ __half g_xm[(size_t)TOKENS*DIM];   // 2048*(x - xh)
__device__ __half g_wh[(size_t)NEXP*DIM];     // W*64
__device__ __half g_wm[(size_t)NEXP*DIM];     // 2048*(W*64 - wh)

// ---------------- fp32 -> (h, scaled residual) fp16 split ----------------
union Pack8h { __half h[8]; uint4 u; };

__global__ __launch_bounds__(256)
void split2_kernel(const float* __restrict__ x, const float* __restrict__ W) {
    const size_t XN8 = (size_t)TOKENS*DIM/8;
    const size_t WN8 = (size_t)NEXP*DIM/8;
    size_t i = (size_t)blockIdx.x*blockDim.x + threadIdx.x;
    const float4* s4; __half *hp, *mp; size_t idx; float scale;
    if (i < XN8)          { s4 = (const float4*)x; hp = g_xh; mp = g_xm; idx = i;     scale = 1.0f;   }
    else if (i < XN8+WN8) { s4 = (const float4*)W; hp = g_wh; mp = g_wm; idx = i-XN8; scale = WSCALE; }
    else return;

    float4 v0 = s4[idx*2], v1 = s4[idx*2+1];
    float v[8] = {v0.x,v0.y,v0.z,v0.w,v1.x,v1.y,v1.z,v1.w};
    Pack8h ph, pm;
    #pragma unroll
    for (int j = 0; j < 8; j++) {
        float a = v[j] * scale;
        __half hb = __float2half_rn(a);
        float r = (a - __half2float(hb)) * RSCALE;   // exact diff, exact pow2 scale
        ph.h[j] = hb;
        pm.h[j] = __float2half_rn(r);                // normal-range fp16
    }
    ((uint4*)hp)[idx] = ph.u;
    ((uint4*)mp)[idx] = pm.u;
}

// ---------------- GEMM (mma.sync fp16, 2 accumulator sets) + routing ----------------
__device__ __forceinline__ uint32_t smem_u32(const void* p) {
    uint32_t r;
    asm("{ .reg .u64 t; cvta.to.shared.u64 t, %1; cvt.u32.u64 %0, t; }" : "=r"(r) : "l"(p));
    return r;
}

__device__ __forceinline__ void ldsm_x4(uint32_t& r0, uint32_t& r1, uint32_t& r2, uint32_t& r3,
                                        uint32_t addr) {
    asm volatile("ldmatrix.sync.aligned.m8n8.x4.shared.b16 {%0,%1,%2,%3}, [%4];"
                 : "=r"(r0), "=r"(r1), "=r"(r2), "=r"(r3) : "r"(addr));
}

__device__ __forceinline__ void mma16816(float* c, const uint32_t* a, const uint32_t* b) {
    asm volatile("mma.sync.aligned.m16n8k16.row.col.f32.f16.f16.f32 "
                 "{%0,%1,%2,%3}, {%4,%5,%6,%7}, {%8,%9}, {%0,%1,%2,%3};"
                 : "+f"(c[0]), "+f"(c[1]), "+f"(c[2]), "+f"(c[3])
                 : "r"(a[0]), "r"(a[1]), "r"(a[2]), "r"(a[3]), "r"(b[0]), "r"(b[1]));
}

__global__ __launch_bounds__(256, 1)
void gemm_route2_kernel(const float* __restrict__ bias, float* __restrict__ out, int out_size) {
    extern __shared__ __align__(1024) char smem[];
    const uint32_t sbase = smem_u32(smem);
    const int tid  = threadIdx.x;
    const int wid  = tid >> 5;
    const int lane = tid & 31;
    const int wm = wid & 1;        // warp m coord (2)
    const int wn = wid >> 1;       // warp n coord (4)
    const int bm = blockIdx.x * BM;

    // products: p0=(xh,wh)->S1  p1=(xh,wm)->S2  p2=(xm,wh)->S2
    const __half* Asrc[3] = { g_xh, g_xh, g_xm };
    const __half* Bsrc[3] = { g_wh, g_wm, g_wh };

    const int arow0 = tid >> 3;        // rows 0..31 (j adds 32)
    const int ac    = tid & 7;         // 16B chunk in row
    const int a_r   = lane & 15;
    const int a_k   = (lane >> 4) * 16;           // bytes
    const int a_x   = (a_r & 7) * 16;
    const int b_r   = (lane & 7) + ((lane >> 4) << 3);
    const int b_k   = ((lane >> 3) & 1) * 16;     // bytes
    const int b_x   = (b_r & 7) * 16;

    // p and sbuf are compile-time at every call site
    auto load_stage = [&](int lchunk, int p, int sbuf) {
        if (lchunk < NCHUNK) {
            const __half* Ag = Asrc[p] + (size_t)bm * DIM + lchunk * KB;
            const __half* Bg = Bsrc[p] + lchunk * KB;
            const uint32_t sA = sbase + sbuf * STAGE_B;
            const uint32_t sB = sA + A_STAGE_B;
            #pragma unroll
            for (int j = 0; j < 2; j++) {
                const int row = arow0 + j * 32;
                const uint32_t dst = sA + row * 128 + ((ac * 16) ^ ((row & 7) * 16));
                const __half* src = Ag + (size_t)row * DIM + ac * 8;
                asm volatile("cp.async.cg.shared.global [%0], [%1], 16;" :: "r"(dst), "l"(src) : "memory");
            }
            #pragma unroll
            for (int j = 0; j < 8; j++) {
                const int row = arow0 + j * 32;
                const uint32_t dst = sB + row * 128 + ((ac * 16) ^ ((row & 7) * 16));
                const __half* src = Bg + (size_t)row * DIM + ac * 8;
                asm volatile("cp.async.cg.shared.global [%0], [%1], 16;" :: "r"(dst), "l"(src) : "memory");
            }
        }
        asm volatile("cp.async.commit_group;" ::: "memory");
    };

    float acc1[2][8][4], acc2[2][8][4];
    #pragma unroll
    for (int i = 0; i < 2; i++)
        #pragma unroll
        for (int j = 0; j < 8; j++)
            #pragma unroll
            for (int q = 0; q < 4; q++) { acc1[i][j][q] = 0.0f; acc2[i][j][q] = 0.0f; }

    load_stage(0, 0, 0);   // ks=0
    load_stage(0, 1, 1);   // ks=1

    for (int chunk = 0; chunk < NCHUNK; chunk++) {
        #pragma unroll
        for (int p = 0; p < 3; p++) {        // ks = 3*chunk + p  ->  sbuf = p
            asm volatile("cp.async.wait_group 1;" ::: "memory");
            __syncthreads();
            // ks+2: chunk' = chunk + (p>=1), p' = (p+2)%3, sbuf' = (p+2)%3
            load_stage(chunk + (p >= 1 ? 1 : 0), (p + 2) % 3, (p + 2) % 3);

            const uint32_t sA = sbase + p * STAGE_B;
            const uint32_t sB = sA + A_STAGE_B;
            #pragma unroll
            for (int st = 0; st < 4; st++) {
                const int bc = st * 32;
                uint32_t a[2][4], b[8][2];
                #pragma unroll
                for (int mt = 0; mt < 2; mt++)
                    ldsm_x4(a[mt][0], a[mt][1], a[mt][2], a[mt][3],
                            sA + (wm * 32 + mt * 16 + a_r) * 128 + ((bc + a_k) ^ a_x));
                #pragma unroll
                for (int bt = 0; bt < 4; bt++)
                    ldsm_x4(b[2*bt][0], b[2*bt][1], b[2*bt+1][0], b[2*bt+1][1],
                            sB + (wn * 64 + bt * 16 + b_r) * 128 + ((bc + b_k) ^ b_x));
                #pragma unroll
                for (int mt = 0; mt < 2; mt++)
                    #pragma unroll
                    for (int nt = 0; nt < 8; nt++)
                        mma16816(p == 0 ? acc1[mt][nt] : acc2[mt][nt], a[mt], b[nt]);
            }
        }
    }

    asm volatile("cp.async.wait_group 0;" ::: "memory");
    __syncthreads();

    // ---- scores -> smem: sigmoid((S1 + S2/2048)/64) ----
    float* sc = (float*)smem;
    {
        const int r0 = lane >> 2;
        const int c0 = (lane & 3) * 2;
        #pragma unroll
        for (int mt = 0; mt < 2; mt++) {
            #pragma unroll
            for (int nt = 0; nt < 8; nt++) {
                const int row = wm * 32 + mt * 16 + r0;
                const int col = wn * 64 + nt * 8 + c0;
                #pragma unroll
                for (int q = 0; q < 4; q++) {
                    const float L = (acc1[mt][nt][q] + acc2[mt][nt][q] * INV_RS) * INV_WSCALE;
                    const int rr = row + (q >> 1) * 8;
                    const int cc = col + (q & 1);
                    sc[rr * SROW + cc] = 1.0f / (1.0f + __expf(-L));
                }
            }
        }
    }
    __syncthreads();

    // ---- fused routing: each warp routes 8 tokens ----
    float4 bc0 = *(const float4*)(bias + lane * 8);
    float4 bc1 = *(const float4*)(bias + lane * 8 + 4);

    for (int i = 0; i < 8; i++) {
        const int tl = wid * 8 + i;
        const int t  = bm + tl;
        const float* srow = sc + (size_t)tl * SROW;

        float sv[8], sbv[8];
        {
            float4 v0 = *(const float4*)(srow + lane * 8);
            float4 v1 = *(const float4*)(srow + lane * 8 + 4);
            sv[0]=v0.x; sv[1]=v0.y; sv[2]=v0.z; sv[3]=v0.w;
            sv[4]=v1.x; sv[5]=v1.y; sv[6]=v1.z; sv[7]=v1.w;
            sbv[0]=sv[0]+bc0.x; sbv[1]=sv[1]+bc0.y; sbv[2]=sv[2]+bc0.z; sbv[3]=sv[3]+bc0.w;
            sbv[4]=sv[4]+bc1.x; sbv[5]=sv[5]+bc1.y; sbv[6]=sv[6]+bc1.z; sbv[7]=sv[7]+bc1.w;
        }

        float a = -INFINITY, b2 = -INFINITY;
        #pragma unroll
        for (int j = 0; j < 8; j++) {
            float v = sbv[j];
            if (v > a)       { b2 = a; a = v; }
            else if (v > b2) { b2 = v; }
        }
        #pragma unroll
        for (int off = 1; off <= 2; off <<= 1) {
            float oa = __shfl_xor_sync(0xffffffffu, a, off);
            float ob = __shfl_xor_sync(0xffffffffu, b2, off);
            float mx = fmaxf(a, oa);
            float s2 = fmaxf(fminf(a, oa), fmaxf(b2, ob));
            a = mx; b2 = s2;
        }
        const float gscore = a + b2;

        float g[8];
        #pragma unroll
        for (int gg = 0; gg < 8; gg++)
            g[gg] = __shfl_sync(0xffffffffu, gscore, gg * 4);

        unsigned gmask = 0;
        #pragma unroll
        for (int r = 0; r < TOPKG; r++) {
            float bv = -INFINITY; int bi = 0;
            #pragma unroll
            for (int gg = 0; gg < 8; gg++) {
                bool sel = !((gmask >> gg) & 1u) && (g[gg] > bv);
                if (sel) { bv = g[gg]; bi = gg; }
            }
            gmask |= 1u << bi;
        }

        const bool keep = (gmask >> (lane >> 2)) & 1u;
        #pragma unroll
        for (int j = 0; j < 8; j++) sbv[j] = keep ? sbv[j] : 0.0f;

        int my_idx = 0; float my_w = 0.0f;
        #pragma unroll
        for (int r = 0; r < TOPK; r++) {
            float lv = sbv[0]; int lj = 0;
            #pragma unroll
            for (int j = 1; j < 8; j++)
                if (sbv[j] > lv) { lv = sbv[j]; lj = j; }
            float v = lv; int e = lane * 8 + lj;
            #pragma unroll
            for (int off = 16; off; off >>= 1) {
                float ov = __shfl_xor_sync(0xffffffffu, v, off);
                int   oe = __shfl_xor_sync(0xffffffffu, e, off);
                if (ov > v || (ov == v && oe < e)) { v = ov; e = oe; }
            }
            float w = 0.0f;
            if ((e >> 3) == lane) {
                const int j = e & 7;
                #pragma unroll
                for (int jj = 0; jj < 8; jj++)
                    if (jj == j) { w = sv[jj]; sbv[jj] = -INFINITY; }
            }
            w = __shfl_sync(0xffffffffu, w, e >> 3);
            if (lane == r) { my_idx = e; my_w = w; }
        }

        float wsum = (lane < TOPK) ? my_w : 0.0f;
        #pragma unroll
        for (int off = 16; off; off >>= 1)
            wsum += __shfl_xor_sync(0xffffffffu, wsum, off);

        if (lane < TOPK) {
            const float wfin = my_w / wsum * ROUTE_SCALE;
            out[(size_t)t * TOPK + lane] = wfin;
            if (out_size >= 2 * TOKENS * TOPK)
                out[(size_t)TOKENS * TOPK + (size_t)t * TOPK + lane] = (float)my_idx;
        }
    }
}

extern "C" void kernel_launch(void* const* d_in, const int* in_sizes, int n_in,
                              void* d_out, int out_size) {
    const float* x    = (const float*)d_in[0];
    const float* W    = (const float*)d_in[1];
    const float* bias = (const float*)d_in[2];

    cudaFuncSetAttribute(gemm_route2_kernel, cudaFuncAttributeMaxDynamicSharedMemorySize, SMEM_TOTAL);

    const size_t n8 = ((size_t)TOKENS*DIM + (size_t)NEXP*DIM) / 8;
    split2_kernel<<<(unsigned)((n8 + 255) / 256), 256>>>(x, W);

    gemm_route2_kernel<<<TOKENS / BM, 256, SMEM_TOTAL>>>(bias, (float*)d_out, out_size);
}

// round 8
// speedup vs baseline: 2.6426x; 1.0803x over previous
#include <cuda_runtime.h>
#include <cuda_fp16.h>
#include <math.h>
#include <stdint.h>

#define TOKENS   8192
#define DIM      4096
#define NEXP     256
#define TOPK     8
#define TOPKG    4
#define ROUTE_SCALE 2.5f
#define WSCALE   64.0f
#define RSCALE   2048.0f            // residual pre-scale (2^11) -> no fp16 subnormals
#define INV_RS   (1.0f/2048.0f)
#define INV_WSCALE (1.0f/64.0f)

#define BM 64
#define BN 256
#define KB 64                       // K elements per chunk
#define NCHUNK (DIM/KB)             // 64

#define A_TILE_B (BM*KB*2)          // 8192 B
#define B_TILE_B (BN*KB*2)          // 32768 B
#define STAGE_B  (2*A_TILE_B + 2*B_TILE_B)   // 81920 B  (Ah Am Bh Bm)
#define SMEM_TOTAL (2*STAGE_B)      // 163840 B
#define SROW 260                    // score smem row stride (floats)

// ---------------- device scratch (fp16 split operands) ----------------
__device__ __half g_xh[(size_t)TOKENS*DIM];
__device__ __half g_xm[(size_t)TOKENS*DIM];   // 2048*(x - xh)
__device__ __half g_wh[(size_t)NEXP*DIM];     // W*64
__device__ __half g_wm[(size_t)NEXP*DIM];     // 2048*(W*64 - wh)

// ---------------- fp32 -> (h, scaled residual) fp16 split ----------------
union Pack8h { __half h[8]; uint4 u; };

__global__ __launch_bounds__(256)
void split2_kernel(const float* __restrict__ x, const float* __restrict__ W) {
    const size_t XN8 = (size_t)TOKENS*DIM/8;
    const size_t WN8 = (size_t)NEXP*DIM/8;
    size_t i = (size_t)blockIdx.x*blockDim.x + threadIdx.x;
    const float4* s4; __half *hp, *mp; size_t idx; float scale;
    if (i < XN8)          { s4 = (const float4*)x; hp = g_xh; mp = g_xm; idx = i;     scale = 1.0f;   }
    else if (i < XN8+WN8) { s4 = (const float4*)W; hp = g_wh; mp = g_wm; idx = i-XN8; scale = WSCALE; }
    else return;

    float4 v0 = s4[idx*2], v1 = s4[idx*2+1];
    float v[8] = {v0.x,v0.y,v0.z,v0.w,v1.x,v1.y,v1.z,v1.w};
    Pack8h ph, pm;
    #pragma unroll
    for (int j = 0; j < 8; j++) {
        float a = v[j] * scale;
        __half hb = __float2half_rn(a);
        float r = (a - __half2float(hb)) * RSCALE;   // exact diff, exact pow2 scale
        ph.h[j] = hb;
        pm.h[j] = __float2half_rn(r);                // normal-range fp16
    }
    ((uint4*)hp)[idx] = ph.u;
    ((uint4*)mp)[idx] = pm.u;
}

// ---------------- GEMM (mma.sync fp16, shared fragments) + routing ----------------
__device__ __forceinline__ uint32_t smem_u32(const void* p) {
    uint32_t r;
    asm("{ .reg .u64 t; cvta.to.shared.u64 t, %1; cvt.u32.u64 %0, t; }" : "=r"(r) : "l"(p));
    return r;
}

__device__ __forceinline__ void ldsm_x4(uint32_t& r0, uint32_t& r1, uint32_t& r2, uint32_t& r3,
                                        uint32_t addr) {
    asm volatile("ldmatrix.sync.aligned.m8n8.x4.shared.b16 {%0,%1,%2,%3}, [%4];"
                 : "=r"(r0), "=r"(r1), "=r"(r2), "=r"(r3) : "r"(addr));
}

__device__ __forceinline__ void mma16816(float* c, const uint32_t* a, const uint32_t* b) {
    asm volatile("mma.sync.aligned.m16n8k16.row.col.f32.f16.f16.f32 "
                 "{%0,%1,%2,%3}, {%4,%5,%6,%7}, {%8,%9}, {%0,%1,%2,%3};"
                 : "+f"(c[0]), "+f"(c[1]), "+f"(c[2]), "+f"(c[3])
                 : "r"(a[0]), "r"(a[1]), "r"(a[2]), "r"(a[3]), "r"(b[0]), "r"(b[1]));
}

__global__ __launch_bounds__(256, 1)
void gemm_route3_kernel(const float* __restrict__ bias, float* __restrict__ out, int out_size) {
    extern __shared__ __align__(1024) char smem[];
    const uint32_t sbase = smem_u32(smem);
    const int tid  = threadIdx.x;
    const int wid  = tid >> 5;
    const int lane = tid & 31;
    const int wm = wid & 1;        // warp m coord (2)
    const int wn = wid >> 1;       // warp n coord (4)
    const int bm = blockIdx.x * BM;

    const int arow0 = tid >> 3;        // rows 0..31 (j adds 32)
    const int ac    = tid & 7;         // 16B chunk in row
    const int a_r   = lane & 15;
    const int a_k   = (lane >> 4) * 16;           // bytes
    const int a_x   = (a_r & 7) * 16;
    const int b_r   = (lane & 7) + ((lane >> 4) << 3);
    const int b_k   = ((lane >> 3) & 1) * 16;     // bytes
    const int b_x   = (b_r & 7) * 16;

    // load one full chunk (Ah, Am, Bh, Bm) into stage s
    auto load_chunk = [&](int c, int s) {
        if (c < NCHUNK) {
            const size_t aoff = (size_t)bm * DIM + c * KB;
            const size_t boff = (size_t)c * KB;
            const uint32_t st = sbase + s * STAGE_B;
            const __half* Asrc[2] = { g_xh + aoff, g_xm + aoff };
            const __half* Bsrc[2] = { g_wh + boff, g_wm + boff };
            #pragma unroll
            for (int v = 0; v < 2; v++) {
                const uint32_t sA = st + v * A_TILE_B;
                #pragma unroll
                for (int j = 0; j < 2; j++) {           // A: 64 rows
                    const int row = arow0 + j * 32;
                    const uint32_t dst = sA + row * 128 + ((ac * 16) ^ ((row & 7) * 16));
                    const __half* src = Asrc[v] + (size_t)row * DIM + ac * 8;
                    asm volatile("cp.async.cg.shared.global [%0], [%1], 16;" :: "r"(dst), "l"(src) : "memory");
                }
                const uint32_t sB = st + 2 * A_TILE_B + v * B_TILE_B;
                #pragma unroll
                for (int j = 0; j < 8; j++) {           // B: 256 rows
                    const int row = arow0 + j * 32;
                    const uint32_t dst = sB + row * 128 + ((ac * 16) ^ ((row & 7) * 16));
                    const __half* src = Bsrc[v] + (size_t)row * DIM + ac * 8;
                    asm volatile("cp.async.cg.shared.global [%0], [%1], 16;" :: "r"(dst), "l"(src) : "memory");
                }
            }
        }
        asm volatile("cp.async.commit_group;" ::: "memory");
    };

    float acc1[2][8][4], acc2[2][8][4];
    #pragma unroll
    for (int i = 0; i < 2; i++)
        #pragma unroll
        for (int j = 0; j < 8; j++)
            #pragma unroll
            for (int q = 0; q < 4; q++) { acc1[i][j][q] = 0.0f; acc2[i][j][q] = 0.0f; }

    load_chunk(0, 0);
    load_chunk(1, 1);

    for (int c = 0; c < NCHUNK; c++) {
        const int s = c & 1;
        asm volatile("cp.async.wait_group 1;" ::: "memory");
        __syncthreads();

        const uint32_t st  = sbase + s * STAGE_B;
        const uint32_t sAh = st;
        const uint32_t sAm = st + A_TILE_B;
        const uint32_t sBh = st + 2 * A_TILE_B;
        const uint32_t sBm = sBh + B_TILE_B;

        #pragma unroll
        for (int kst = 0; kst < 4; kst++) {            // 4 k16 steps per chunk
            const int bc = kst * 32;
            uint32_t ah[2][4], am[2][4], bh[8][2], bmf[8][2];
            #pragma unroll
            for (int mt = 0; mt < 2; mt++) {
                const uint32_t rofs = (wm * 32 + mt * 16 + a_r) * 128 + ((bc + a_k) ^ a_x);
                ldsm_x4(ah[mt][0], ah[mt][1], ah[mt][2], ah[mt][3], sAh + rofs);
                ldsm_x4(am[mt][0], am[mt][1], am[mt][2], am[mt][3], sAm + rofs);
            }
            #pragma unroll
            for (int bt = 0; bt < 4; bt++) {
                const uint32_t rofs = (wn * 64 + bt * 16 + b_r) * 128 + ((bc + b_k) ^ b_x);
                ldsm_x4(bh[2*bt][0],  bh[2*bt][1],  bh[2*bt+1][0],  bh[2*bt+1][1],  sBh + rofs);
                ldsm_x4(bmf[2*bt][0], bmf[2*bt][1], bmf[2*bt+1][0], bmf[2*bt+1][1], sBm + rofs);
            }
            #pragma unroll
            for (int mt = 0; mt < 2; mt++)
                #pragma unroll
                for (int nt = 0; nt < 8; nt++) {
                    mma16816(acc1[mt][nt], ah[mt], bh[nt]);    // hh -> S1
                    mma16816(acc2[mt][nt], ah[mt], bmf[nt]);   // hm -> S2
                    mma16816(acc2[mt][nt], am[mt], bh[nt]);    // mh -> S2
                }
        }

        __syncthreads();                 // all warps done reading stage s
        load_chunk(c + 2, s);
    }

    asm volatile("cp.async.wait_group 0;" ::: "memory");
    __syncthreads();

    // ---- scores -> smem: sigmoid((S1 + S2/2048)/64) ----
    float* sc = (float*)smem;
    {
        const int r0 = lane >> 2;
        const int c0 = (lane & 3) * 2;
        #pragma unroll
        for (int mt = 0; mt < 2; mt++) {
            #pragma unroll
            for (int nt = 0; nt < 8; nt++) {
                const int row = wm * 32 + mt * 16 + r0;
                const int col = wn * 64 + nt * 8 + c0;
                #pragma unroll
                for (int q = 0; q < 4; q++) {
                    const float L = (acc1[mt][nt][q] + acc2[mt][nt][q] * INV_RS) * INV_WSCALE;
                    const int rr = row + (q >> 1) * 8;
                    const int cc = col + (q & 1);
                    sc[rr * SROW + cc] = 1.0f / (1.0f + __expf(-L));
                }
            }
        }
    }
    __syncthreads();

    // ---- fused routing: each warp routes 8 tokens ----
    float4 bc0 = *(const float4*)(bias + lane * 8);
    float4 bc1 = *(const float4*)(bias + lane * 8 + 4);

    for (int i = 0; i < 8; i++) {
        const int tl = wid * 8 + i;
        const int t  = bm + tl;
        const float* srow = sc + (size_t)tl * SROW;

        float sv[8], sbv[8];
        {
            float4 v0 = *(const float4*)(srow + lane * 8);
            float4 v1 = *(const float4*)(srow + lane * 8 + 4);
            sv[0]=v0.x; sv[1]=v0.y; sv[2]=v0.z; sv[3]=v0.w;
            sv[4]=v1.x; sv[5]=v1.y; sv[6]=v1.z; sv[7]=v1.w;
            sbv[0]=sv[0]+bc0.x; sbv[1]=sv[1]+bc0.y; sbv[2]=sv[2]+bc0.z; sbv[3]=sv[3]+bc0.w;
            sbv[4]=sv[4]+bc1.x; sbv[5]=sv[5]+bc1.y; sbv[6]=sv[6]+bc1.z; sbv[7]=sv[7]+bc1.w;
        }

        float a = -INFINITY, b2 = -INFINITY;
        #pragma unroll
        for (int j = 0; j < 8; j++) {
            float v = sbv[j];
            if (v > a)       { b2 = a; a = v; }
            else if (v > b2) { b2 = v; }
        }
        #pragma unroll
        for (int off = 1; off <= 2; off <<= 1) {
            float oa = __shfl_xor_sync(0xffffffffu, a, off);
            float ob = __shfl_xor_sync(0xffffffffu, b2, off);
            float mx = fmaxf(a, oa);
            float s2 = fmaxf(fminf(a, oa), fmaxf(b2, ob));
            a = mx; b2 = s2;
        }
        const float gscore = a + b2;

        float g[8];
        #pragma unroll
        for (int gg = 0; gg < 8; gg++)
            g[gg] = __shfl_sync(0xffffffffu, gscore, gg * 4);

        unsigned gmask = 0;
        #pragma unroll
        for (int r = 0; r < TOPKG; r++) {
            float bv = -INFINITY; int bi = 0;
            #pragma unroll
            for (int gg = 0; gg < 8; gg++) {
                bool sel = !((gmask >> gg) & 1u) && (g[gg] > bv);
                if (sel) { bv = g[gg]; bi = gg; }
            }
            gmask |= 1u << bi;
        }

        const bool keep = (gmask >> (lane >> 2)) & 1u;
        #pragma unroll
        for (int j = 0; j < 8; j++) sbv[j] = keep ? sbv[j] : 0.0f;

        int my_idx = 0; float my_w = 0.0f;
        #pragma unroll
        for (int r = 0; r < TOPK; r++) {
            float lv = sbv[0]; int lj = 0;
            #pragma unroll
            for (int j = 1; j < 8; j++)
                if (sbv[j] > lv) { lv = sbv[j]; lj = j; }
            float v = lv; int e = lane * 8 + lj;
            #pragma unroll
            for (int off = 16; off; off >>= 1) {
                float ov = __shfl_xor_sync(0xffffffffu, v, off);
                int   oe = __shfl_xor_sync(0xffffffffu, e, off);
                if (ov > v || (ov == v && oe < e)) { v = ov; e = oe; }
            }
            float w = 0.0f;
            if ((e >> 3) == lane) {
                const int j = e & 7;
                #pragma unroll
                for (int jj = 0; jj < 8; jj++)
                    if (jj == j) { w = sv[jj]; sbv[jj] = -INFINITY; }
            }
            w = __shfl_sync(0xffffffffu, w, e >> 3);
            if (lane == r) { my_idx = e; my_w = w; }
        }

        float wsum = (lane < TOPK) ? my_w : 0.0f;
        #pragma unroll
        for (int off = 16; off; off >>= 1)
            wsum += __shfl_xor_sync(0xffffffffu, wsum, off);

        if (lane < TOPK) {
            const float wfin = my_w / wsum * ROUTE_SCALE;
            out[(size_t)t * TOPK + lane] = wfin;
            if (out_size >= 2 * TOKENS * TOPK)
                out[(size_t)TOKENS * TOPK + (size_t)t * TOPK + lane] = (float)my_idx;
        }
    }
}

extern "C" void kernel_launch(void* const* d_in, const int* in_sizes, int n_in,
                              void* d_out, int out_size) {
    const float* x    = (const float*)d_in[0];
    const float* W    = (const float*)d_in[1];
    const float* bias = (const float*)d_in[2];

    cudaFuncSetAttribute(gemm_route3_kernel, cudaFuncAttributeMaxDynamicSharedMemorySize, SMEM_TOTAL);

    const size_t n8 = ((size_t)TOKENS*DIM + (size_t)NEXP*DIM) / 8;
    split2_kernel<<<(unsigned)((n8 + 255) / 256), 256>>>(x, W);

    gemm_route3_kernel<<<TOKENS / BM, 256, SMEM_TOTAL>>>(bias, (float*)d_out, out_size);
}

// round 10
// speedup vs baseline: 2.7033x; 1.0230x over previous
#include <cuda_runtime.h>
#include <cuda_fp16.h>
#include <math.h>
#include <stdint.h>

#define TOKENS   8192
#define DIM      4096
#define NEXP     256
#define TOPK     8
#define TOPKG    4
#define ROUTE_SCALE 2.5f
#define WSCALE   64.0f
#define RSCALE   2048.0f            // residual pre-scale (2^11) -> no fp16 subnormals
#define INV_RS   (1.0f/2048.0f)
#define INV_WSCALE (1.0f/64.0f)

#define BM 64
#define BN 256
#define KB 64                       // K elements per chunk
#define NCHUNK (DIM/KB)             // 64
#define NTHREADS 512

#define A_TILE_B (BM*KB*2)          // 8192 B
#define B_TILE_B (BN*KB*2)          // 32768 B
#define STAGE_B  (2*A_TILE_B + 2*B_TILE_B)   // 81920 B  (Ah Am Bh Bm)
#define SMEM_TOTAL (2*STAGE_B)      // 163840 B
#define SROW 260                    // score smem row stride (floats)

// ---------------- device scratch (fp16 split operands) ----------------
__device__ __half g_xh[(size_t)TOKENS*DIM];
__device__ __half g_xm[(size_t)TOKENS*DIM];   // 2048*(x - xh)
__device__ __half g_wh[(size_t)NEXP*DIM];     // W*64
__device__ __half g_wm[(size_t)NEXP*DIM];     // 2048*(W*64 - wh)

// ---------------- fp32 -> (h, scaled residual) fp16 split ----------------
union Pack8h { __half h[8]; uint4 u; };

__global__ __launch_bounds__(256)
void split2_kernel(const float* __restrict__ x, const float* __restrict__ W) {
    const size_t XN8 = (size_t)TOKENS*DIM/8;
    const size_t WN8 = (size_t)NEXP*DIM/8;
    size_t i = (size_t)blockIdx.x*blockDim.x + threadIdx.x;
    const float4* s4; __half *hp, *mp; size_t idx; float scale;
    if (i < XN8)          { s4 = (const float4*)x; hp = g_xh; mp = g_xm; idx = i;     scale = 1.0f;   }
    else if (i < XN8+WN8) { s4 = (const float4*)W; hp = g_wh; mp = g_wm; idx = i-XN8; scale = WSCALE; }
    else return;

    float4 v0 = s4[idx*2], v1 = s4[idx*2+1];
    float v[8] = {v0.x,v0.y,v0.z,v0.w,v1.x,v1.y,v1.z,v1.w};
    Pack8h ph, pm;
    #pragma unroll
    for (int j = 0; j < 8; j++) {
        float a = v[j] * scale;
        __half hb = __float2half_rn(a);
        float r = (a - __half2float(hb)) * RSCALE;   // exact diff, exact pow2 scale
        ph.h[j] = hb;
        pm.h[j] = __float2half_rn(r);                // normal-range fp16
    }
    ((uint4*)hp)[idx] = ph.u;
    ((uint4*)mp)[idx] = pm.u;
}

// ---------------- GEMM (mma.sync fp16, 16 warps) + routing ----------------
__device__ __forceinline__ uint32_t smem_u32(const void* p) {
    uint32_t r;
    asm("{ .reg .u64 t; cvta.to.shared.u64 t, %1; cvt.u32.u64 %0, t; }" : "=r"(r) : "l"(p));
    return r;
}

__device__ __forceinline__ void ldsm_x4(uint32_t& r0, uint32_t& r1, uint32_t& r2, uint32_t& r3,
                                        uint32_t addr) {
    asm volatile("ldmatrix.sync.aligned.m8n8.x4.shared.b16 {%0,%1,%2,%3}, [%4];"
                 : "=r"(r0), "=r"(r1), "=r"(r2), "=r"(r3) : "r"(addr));
}

__device__ __forceinline__ void mma16816(float* c, const uint32_t* a, const uint32_t* b) {
    asm volatile("mma.sync.aligned.m16n8k16.row.col.f32.f16.f16.f32 "
                 "{%0,%1,%2,%3}, {%4,%5,%6,%7}, {%8,%9}, {%0,%1,%2,%3};"
                 : "+f"(c[0]), "+f"(c[1]), "+f"(c[2]), "+f"(c[3])
                 : "r"(a[0]), "r"(a[1]), "r"(a[2]), "r"(a[3]), "r"(b[0]), "r"(b[1]));
}

__global__ __launch_bounds__(NTHREADS, 1)
void gemm_route4_kernel(const float* __restrict__ bias, float* __restrict__ out, int out_size) {
    extern __shared__ __align__(1024) char smem[];
    const uint32_t sbase = smem_u32(smem);
    const int tid  = threadIdx.x;
    const int wid  = tid >> 5;
    const int lane = tid & 31;
    const int wm = wid & 3;        // warp m coord (4) -> 16 rows each
    const int wn = wid >> 2;       // warp n coord (4) -> 64 cols each
    const int bm = blockIdx.x * BM;

    const int a_r   = lane & 15;
    const int a_k   = (lane >> 4) * 16;           // bytes
    const int a_x   = (a_r & 7) * 16;
    const int b_r   = (lane & 7) + ((lane >> 4) << 3);
    const int b_k   = ((lane >> 3) & 1) * 16;     // bytes
    const int b_x   = (b_r & 7) * 16;

    // load one full chunk (Ah, Am, Bh, Bm) into stage s
    auto load_chunk = [&](int c, int s) {
        if (c < NCHUNK) {
            const size_t aoff = (size_t)bm * DIM + c * KB;
            const size_t boff = (size_t)c * KB;
            const uint32_t st = sbase + s * STAGE_B;
            // A: 2 tiles x 64 rows x 8 chunks = 1024 items -> 2 per thread
            #pragma unroll
            for (int j = 0; j < 2; j++) {
                const int idx = tid + NTHREADS * j;
                const int v   = idx >> 9;
                const int r8  = idx & 511;
                const int row = r8 >> 3;
                const int ch  = r8 & 7;
                const uint32_t dst = st + v * A_TILE_B + row * 128 + ((ch * 16) ^ ((row & 7) * 16));
                const __half* src = (v ? g_xm : g_xh) + aoff + (size_t)row * DIM + ch * 8;
                asm volatile("cp.async.cg.shared.global [%0], [%1], 16;" :: "r"(dst), "l"(src) : "memory");
            }
            // B: 2 tiles x 256 rows x 8 chunks = 4096 items -> 8 per thread
            #pragma unroll
            for (int j = 0; j < 8; j++) {
                const int idx = tid + NTHREADS * j;
                const int v   = idx >> 11;
                const int r8  = idx & 2047;
                const int row = r8 >> 3;
                const int ch  = r8 & 7;
                const uint32_t dst = st + 2 * A_TILE_B + v * B_TILE_B + row * 128 + ((ch * 16) ^ ((row & 7) * 16));
                const __half* src = (v ? g_wm : g_wh) + boff + (size_t)row * DIM + ch * 8;
                asm volatile("cp.async.cg.shared.global [%0], [%1], 16;" :: "r"(dst), "l"(src) : "memory");
            }
        }
        asm volatile("cp.async.commit_group;" ::: "memory");
    };

    float acc1[8][4], acc2[8][4];
    #pragma unroll
    for (int j = 0; j < 8; j++)
        #pragma unroll
        for (int q = 0; q < 4; q++) { acc1[j][q] = 0.0f; acc2[j][q] = 0.0f; }

    load_chunk(0, 0);
    load_chunk(1, 1);

    for (int c = 0; c < NCHUNK; c++) {
        const int s = c & 1;
        asm volatile("cp.async.wait_group 1;" ::: "memory");
        __syncthreads();

        const uint32_t st  = sbase + s * STAGE_B;
        const uint32_t sAh = st;
        const uint32_t sAm = st + A_TILE_B;
        const uint32_t sBh = st + 2 * A_TILE_B;
        const uint32_t sBm = sBh + B_TILE_B;

        #pragma unroll
        for (int kst = 0; kst < 4; kst++) {            // 4 k16 steps per chunk
            const int bc = kst * 32;
            uint32_t ah[4], am[4], bh[8][2], bmf[8][2];
            {
                const uint32_t rofs = (wm * 16 + a_r) * 128 + ((bc + a_k) ^ a_x);
                ldsm_x4(ah[0], ah[1], ah[2], ah[3], sAh + rofs);
                ldsm_x4(am[0], am[1], am[2], am[3], sAm + rofs);
            }
            #pragma unroll
            for (int bt = 0; bt < 4; bt++) {
                const uint32_t rofs = (wn * 64 + bt * 16 + b_r) * 128 + ((bc + b_k) ^ b_x);
                ldsm_x4(bh[2*bt][0],  bh[2*bt][1],  bh[2*bt+1][0],  bh[2*bt+1][1],  sBh + rofs);
                ldsm_x4(bmf[2*bt][0], bmf[2*bt][1], bmf[2*bt+1][0], bmf[2*bt+1][1], sBm + rofs);
            }
            #pragma unroll
            for (int nt = 0; nt < 8; nt++) {
                mma16816(acc1[nt], ah, bh[nt]);    // hh -> S1
                mma16816(acc2[nt], ah, bmf[nt]);   // hm -> S2
                mma16816(acc2[nt], am, bh[nt]);    // mh -> S2
            }
        }

        __syncthreads();                 // all warps done reading stage s
        load_chunk(c + 2, s);
    }

    asm volatile("cp.async.wait_group 0;" ::: "memory");
    __syncthreads();

    // ---- scores -> smem: sigmoid((S1 + S2/2048)/64) ----
    float* sc = (float*)smem;
    {
        const int r0 = lane >> 2;
        const int c0 = (lane & 3) * 2;
        #pragma unroll
        for (int nt = 0; nt < 8; nt++) {
            const int row = wm * 16 + r0;
            const int col = wn * 64 + nt * 8 + c0;
            #pragma unroll
            for (int q = 0; q < 4; q++) {
                const float L = (acc1[nt][q] + acc2[nt][q] * INV_RS) * INV_WSCALE;
                const int rr = row + (q >> 1) * 8;
                const int cc = col + (q & 1);
                sc[rr * SROW + cc] = 1.0f / (1.0f + __expf(-L));
            }
        }
    }
    __syncthreads();

    // ---- fused routing: each warp routes 4 tokens ----
    float4 bc0 = *(const float4*)(bias + lane * 8);
    float4 bc1 = *(const float4*)(bias + lane * 8 + 4);

    for (int i = 0; i < 4; i++) {
        const int tl = wid * 4 + i;
        const int t  = bm + tl;
        const float* srow = sc + (size_t)tl * SROW;

        float sv[8], sbv[8];
        {
            float4 v0 = *(const float4*)(srow + lane * 8);
            float4 v1 = *(const float4*)(srow + lane * 8 + 4);
            sv[0]=v0.x; sv[1]=v0.y; sv[2]=v0.z; sv[3]=v0.w;
            sv[4]=v1.x; sv[5]=v1.y; sv[6]=v1.z; sv[7]=v1.w;
            sbv[0]=sv[0]+bc0.x; sbv[1]=sv[1]+bc0.y; sbv[2]=sv[2]+bc0.z; sbv[3]=sv[3]+bc0.w;
            sbv[4]=sv[4]+bc1.x; sbv[5]=sv[5]+bc1.y; sbv[6]=sv[6]+bc1.z; sbv[7]=sv[7]+bc1.w;
        }

        float a = -INFINITY, b2 = -INFINITY;
        #pragma unroll
        for (int j = 0; j < 8; j++) {
            float v = sbv[j];
            if (v > a)       { b2 = a; a = v; }
            else if (v > b2) { b2 = v; }
        }
        #pragma unroll
        for (int off = 1; off <= 2; off <<= 1) {
            float oa = __shfl_xor_sync(0xffffffffu, a, off);
            float ob = __shfl_xor_sync(0xffffffffu, b2, off);
            float mx = fmaxf(a, oa);
            float s2 = fmaxf(fminf(a, oa), fmaxf(b2, ob));
            a = mx; b2 = s2;
        }
        const float gscore = a + b2;

        float g[8];
        #pragma unroll
        for (int gg = 0; gg < 8; gg++)
            g[gg] = __shfl_sync(0xffffffffu, gscore, gg * 4);

        unsigned gmask = 0;
        #pragma unroll
        for (int r = 0; r < TOPKG; r++) {
            float bv = -INFINITY; int bi = 0;
            #pragma unroll
            for (int gg = 0; gg < 8; gg++) {
                bool sel = !((gmask >> gg) & 1u) && (g[gg] > bv);
                if (sel) { bv = g[gg]; bi = gg; }
            }
            gmask |= 1u << bi;
        }

        const bool keep = (gmask >> (lane >> 2)) & 1u;
        #pragma unroll
        for (int j = 0; j < 8; j++) sbv[j] = keep ? sbv[j] : 0.0f;

        int my_idx = 0; float my_w = 0.0f;
        #pragma unroll
        for (int r = 0; r < TOPK; r++) {
            float lv = sbv[0]; int lj = 0;
            #pragma unroll
            for (int j = 1; j < 8; j++)
                if (sbv[j] > lv) { lv = sbv[j]; lj = j; }
            float v = lv; int e = lane * 8 + lj;
            #pragma unroll
            for (int off = 16; off; off >>= 1) {
                float ov = __shfl_xor_sync(0xffffffffu, v, off);
                int   oe = __shfl_xor_sync(0xffffffffu, e, off);
                if (ov > v || (ov == v && oe < e)) { v = ov; e = oe; }
            }
            float w = 0.0f;
            if ((e >> 3) == lane) {
                const int j = e & 7;
                #pragma unroll
                for (int jj = 0; jj < 8; jj++)
                    if (jj == j) { w = sv[jj]; sbv[jj] = -INFINITY; }
            }
            w = __shfl_sync(0xffffffffu, w, e >> 3);
            if (lane == r) { my_idx = e; my_w = w; }
        }

        float wsum = (lane < TOPK) ? my_w : 0.0f;
        #pragma unroll
        for (int off = 16; off; off >>= 1)
            wsum += __shfl_xor_sync(0xffffffffu, wsum, off);

        if (lane < TOPK) {
            const float wfin = my_w / wsum * ROUTE_SCALE;
            out[(size_t)t * TOPK + lane] = wfin;
            if (out_size >= 2 * TOKENS * TOPK)
                out[(size_t)TOKENS * TOPK + (size_t)t * TOPK + lane] = (float)my_idx;
        }
    }
}

extern "C" void kernel_launch(void* const* d_in, const int* in_sizes, int n_in,
                              void* d_out, int out_size) {
    const float* x    = (const float*)d_in[0];
    const float* W    = (const float*)d_in[1];
    const float* bias = (const float*)d_in[2];

    cudaFuncSetAttribute(gemm_route4_kernel, cudaFuncAttributeMaxDynamicSharedMemorySize, SMEM_TOTAL);

    const size_t n8 = ((size_t)TOKENS*DIM + (size_t)NEXP*DIM) / 8;
    split2_kernel<<<(unsigned)((n8 + 255) / 256), 256>>>(x, W);

    gemm_route4_kernel<<<TOKENS / BM, NTHREADS, SMEM_TOTAL>>>(bias, (float*)d_out, out_size);
}